// round 1
// baseline (speedup 1.0000x reference)
#include <cuda_runtime.h>
#include <cfloat>

#define BATCH 8
#define NPT   1024
#define KNN   20
#define EPSV  1e-6f
#define NSLOPE 0.2f
#define CTOT  169   // 21+21+42+85 concat channels

// -------- scratch (no allocations allowed) --------
__device__ float g_feat[BATCH * CTOT * 3 * NPT];   // concat feature buffer [B][169][3][N]
__device__ float g_xx[BATCH * NPT];
__device__ int   g_idx[BATCH * NPT * KNN];

// ================= squared norms =================
__global__ void xx_kernel(const float* __restrict__ cur, int Ctot, int coff, int D)
{
    int idx = blockIdx.x * blockDim.x + threadIdx.x;
    if (idx >= BATCH * NPT) return;
    int b = idx >> 10, n = idx & (NPT - 1);
    const float* base = cur + (size_t)(b * Ctot + coff) * 3 * NPT;
    float s = 0.f;
    for (int f = 0; f < D; f++) { float v = base[f * NPT + n]; s += v * v; }
    g_xx[idx] = s;
}

// ================= knn + top-k =================
// block handles 8 query points of one batch; warp w does top-k for row w
__global__ void knn_kernel(const float* __restrict__ cur, int Ctot, int coff, int D)
{
    const int TI = 8;
    __shared__ float sxi[TI][128];
    __shared__ float sxxi[TI];
    __shared__ float sdist[TI][NPT];

    int blk = blockIdx.x;
    int b   = blk / (NPT / TI);
    int i0  = (blk % (NPT / TI)) * TI;
    int tid = threadIdx.x;
    const float* base = cur + (size_t)(b * Ctot + coff) * 3 * NPT;

    for (int t = tid; t < TI * D; t += blockDim.x) {
        int ii = t / D, f = t - ii * D;
        sxi[ii][f] = base[f * NPT + i0 + ii];
    }
    if (tid < TI) sxxi[tid] = g_xx[b * NPT + i0 + tid];
    __syncthreads();

    for (int j = tid; j < NPT; j += blockDim.x) {
        float acc[TI];
        #pragma unroll
        for (int ii = 0; ii < TI; ii++) acc[ii] = 0.f;
        for (int f = 0; f < D; f++) {
            float xv = base[f * NPT + j];
            #pragma unroll
            for (int ii = 0; ii < TI; ii++) acc[ii] += sxi[ii][f] * xv;
        }
        float xxj = g_xx[b * NPT + j];
        #pragma unroll
        for (int ii = 0; ii < TI; ii++)
            sdist[ii][j] = 2.f * acc[ii] - sxxi[ii] - xxj;
    }
    __syncthreads();

    int w = tid >> 5, lane = tid & 31;
    if (w < TI) {
        float* row = sdist[w];
        int ob = (b * NPT + i0 + w) * KNN;
        for (int it = 0; it < KNN; it++) {
            float best = -FLT_MAX; int bi = NPT;
            for (int j = lane; j < NPT; j += 32) {
                float v = row[j];
                if (v > best) { best = v; bi = j; }   // ascending j => first (smallest idx) kept on ties
            }
            #pragma unroll
            for (int s = 16; s; s >>= 1) {
                float ov = __shfl_down_sync(0xffffffffu, best, s);
                int   oi = __shfl_down_sync(0xffffffffu, bi,   s);
                if (ov > best || (ov == best && oi < bi)) { best = ov; bi = oi; }
            }
            bi = __shfl_sync(0xffffffffu, bi, 0);
            if (lane == 0) g_idx[ob + it] = bi;
            row[bi] = -FLT_MAX;
            __syncwarp();
        }
    }
}

// ========== fused graph-feature + VN linear-leakyReLU + mean over k ==========
// g channels: [0,CIN) = nbr - center, [CIN,2CIN) = center.
// p_{o,j} = sum_c WfL[o,c]*diff_{c,j} + pconst[o],  pconst = sum_c WfR[o,c]*x_n
template <int CIN, int COUT>
__global__ void vn_edge_kernel(const float* __restrict__ cur, int Ctot, int coff,
                               const float* __restrict__ Wf, const float* __restrict__ Wd,
                               int ooff)
{
    const int IN2   = 2 * CIN;
    const int PAIRS = COUT * KNN;
    extern __shared__ float sm[];
    float2* sW   = (float2*)sm;                       // [CIN][COUT] (wf_left, wd_left)
    float*  sWfr = sm + 2 * CIN * COUT;               // [COUT][CIN] right halves
    float*  sWdr = sWfr + CIN * COUT;
    float4* sdif = (float4*)(sWdr + CIN * COUT);      // [CIN][KNN]
    float*  sxn  = (float*)(sdif + CIN * KNN);        // [3*CIN]
    float*  spc  = sxn + 3 * CIN;                     // [3*COUT]
    float*  sdc  = spc + 3 * COUT;
    float*  sacc = sdc + 3 * COUT;
    int*    sidx = (int*)(sacc + 3 * COUT);           // [KNN]

    int tid = threadIdx.x;
    for (int t = tid; t < CIN * COUT; t += blockDim.x) {
        int c = t / COUT, o = t - c * COUT;
        sW[c * COUT + o] = make_float2(Wf[o * IN2 + c], Wd[o * IN2 + c]);
        sWfr[o * CIN + c] = Wf[o * IN2 + CIN + c];
        sWdr[o * CIN + c] = Wd[o * IN2 + CIN + c];
    }
    __syncthreads();

    for (int pt = blockIdx.x; pt < BATCH * NPT; pt += gridDim.x) {
        int b = pt >> 10, n = pt & (NPT - 1);
        const float* base = cur + (size_t)(b * Ctot + coff) * 3 * NPT;

        for (int t = tid; t < 3 * COUT; t += blockDim.x) sacc[t] = 0.f;
        for (int t = tid; t < 3 * CIN;  t += blockDim.x) sxn[t] = base[t * NPT + n];
        if (tid < KNN) sidx[tid] = g_idx[pt * KNN + tid];
        __syncthreads();

        for (int t = tid; t < CIN * KNN; t += blockDim.x) {
            int c = t / KNN, j = t - c * KNN;
            int nj = sidx[j];
            float4 dv;
            dv.x = base[(c * 3 + 0) * NPT + nj] - sxn[c * 3 + 0];
            dv.y = base[(c * 3 + 1) * NPT + nj] - sxn[c * 3 + 1];
            dv.z = base[(c * 3 + 2) * NPT + nj] - sxn[c * 3 + 2];
            dv.w = 0.f;
            sdif[c * KNN + j] = dv;
        }
        for (int o = tid; o < COUT; o += blockDim.x) {
            float p0 = 0, p1 = 0, p2 = 0, q0 = 0, q1 = 0, q2 = 0;
            for (int c = 0; c < CIN; c++) {
                float x0 = sxn[c * 3], x1 = sxn[c * 3 + 1], x2 = sxn[c * 3 + 2];
                float wf = sWfr[o * CIN + c], wd = sWdr[o * CIN + c];
                p0 += wf * x0; p1 += wf * x1; p2 += wf * x2;
                q0 += wd * x0; q1 += wd * x1; q2 += wd * x2;
            }
            spc[o * 3] = p0; spc[o * 3 + 1] = p1; spc[o * 3 + 2] = p2;
            sdc[o * 3] = q0; sdc[o * 3 + 1] = q1; sdc[o * 3 + 2] = q2;
        }
        __syncthreads();

        for (int p = tid; p < PAIRS; p += blockDim.x) {
            int o = p / KNN, j = p - o * KNN;
            float p0 = spc[o * 3], p1 = spc[o * 3 + 1], p2 = spc[o * 3 + 2];
            float d0 = sdc[o * 3], d1 = sdc[o * 3 + 1], d2 = sdc[o * 3 + 2];
            #pragma unroll 4
            for (int c = 0; c < CIN; c++) {
                float2 w  = sW[c * COUT + o];
                float4 dv = sdif[c * KNN + j];
                p0 += w.x * dv.x; p1 += w.x * dv.y; p2 += w.x * dv.z;
                d0 += w.y * dv.x; d1 += w.y * dv.y; d2 += w.y * dv.z;
            }
            float dot = p0 * d0 + p1 * d1 + p2 * d2;
            float dsq = d0 * d0 + d1 * d1 + d2 * d2;
            float r0, r1, r2;
            if (dot >= 0.f) { r0 = p0; r1 = p1; r2 = p2; }
            else {
                float s = dot / (dsq + EPSV);
                r0 = NSLOPE * p0 + (1.f - NSLOPE) * (p0 - s * d0);
                r1 = NSLOPE * p1 + (1.f - NSLOPE) * (p1 - s * d1);
                r2 = NSLOPE * p2 + (1.f - NSLOPE) * (p2 - s * d2);
            }
            atomicAdd(&sacc[o * 3 + 0], r0);
            atomicAdd(&sacc[o * 3 + 1], r1);
            atomicAdd(&sacc[o * 3 + 2], r2);
        }
        __syncthreads();

        float* outp = g_feat + ((size_t)(b * CTOT + ooff) * 3) * NPT + n;
        const float invK = 1.f / KNN;
        for (int t = tid; t < 3 * COUT; t += blockDim.x) outp[t * NPT] = sacc[t] * invK;
        __syncthreads();
    }
}

// ========== final VN layer (no graph) + mean over N ==========
__global__ void final_kernel(const float* __restrict__ Wf, const float* __restrict__ Wd,
                             float* __restrict__ out)
{
    const int OT = 11;               // 341 = 31 * 11
    const int CI = CTOT;
    __shared__ float sWf[OT * CI];
    __shared__ float sWd[CI];
    __shared__ float sacc[OT * 3];
    int b  = blockIdx.x / 31;
    int o0 = (blockIdx.x % 31) * OT;
    int tid = threadIdx.x;

    for (int t = tid; t < OT * CI; t += blockDim.x) {
        int o = t / CI, c = t - o * CI;
        sWf[t] = Wf[(o0 + o) * CI + c];
    }
    for (int t = tid; t < CI; t += blockDim.x) sWd[t] = Wd[t];
    if (tid < OT * 3) sacc[tid] = 0.f;
    __syncthreads();

    float sum[OT][3];
    #pragma unroll
    for (int o = 0; o < OT; o++) { sum[o][0] = sum[o][1] = sum[o][2] = 0.f; }

    const float* base = g_feat + (size_t)b * CTOT * 3 * NPT;
    for (int n = tid; n < NPT; n += blockDim.x) {
        float p[OT][3];
        #pragma unroll
        for (int o = 0; o < OT; o++) { p[o][0] = p[o][1] = p[o][2] = 0.f; }
        float d0 = 0, d1 = 0, d2 = 0;
        for (int c = 0; c < CI; c++) {
            float x0 = base[(c * 3 + 0) * NPT + n];
            float x1 = base[(c * 3 + 1) * NPT + n];
            float x2 = base[(c * 3 + 2) * NPT + n];
            float wd = sWd[c];
            d0 += wd * x0; d1 += wd * x1; d2 += wd * x2;
            #pragma unroll
            for (int o = 0; o < OT; o++) {
                float w = sWf[o * CI + c];
                p[o][0] += w * x0; p[o][1] += w * x1; p[o][2] += w * x2;
            }
        }
        float inv = 1.f / (d0 * d0 + d1 * d1 + d2 * d2 + EPSV);
        #pragma unroll
        for (int o = 0; o < OT; o++) {
            float dot = p[o][0] * d0 + p[o][1] * d1 + p[o][2] * d2;
            float r0, r1, r2;
            if (dot >= 0.f) { r0 = p[o][0]; r1 = p[o][1]; r2 = p[o][2]; }
            else {
                float s = dot * inv;
                r0 = NSLOPE * p[o][0] + (1.f - NSLOPE) * (p[o][0] - s * d0);
                r1 = NSLOPE * p[o][1] + (1.f - NSLOPE) * (p[o][1] - s * d1);
                r2 = NSLOPE * p[o][2] + (1.f - NSLOPE) * (p[o][2] - s * d2);
            }
            sum[o][0] += r0; sum[o][1] += r1; sum[o][2] += r2;
        }
    }
    #pragma unroll
    for (int o = 0; o < OT; o++)
        #pragma unroll
        for (int dd = 0; dd < 3; dd++) {
            float v = sum[o][dd];
            #pragma unroll
            for (int s = 16; s; s >>= 1) v += __shfl_down_sync(0xffffffffu, v, s);
            if ((tid & 31) == 0) atomicAdd(&sacc[o * 3 + dd], v);
        }
    __syncthreads();
    if (tid < OT * 3) out[b * 341 * 3 + o0 * 3 + tid] = sacc[tid] * (1.f / NPT);
}

// ================= launch =================
static size_t vn_smem(int CIN, int COUT)
{
    return (size_t)(4 * CIN * COUT + 4 * CIN * KNN + 3 * CIN + 9 * COUT + KNN) * 4;
}

extern "C" void kernel_launch(void* const* d_in, const int* in_sizes, int n_in,
                              void* d_out, int out_size)
{
    const float* x   = (const float*)d_in[0];
    const float* Wf0 = (const float*)d_in[1];
    const float* Wd0 = (const float*)d_in[2];
    const float* Wf1 = (const float*)d_in[3];
    const float* Wd1 = (const float*)d_in[4];
    const float* Wf2 = (const float*)d_in[5];
    const float* Wd2 = (const float*)d_in[6];
    const float* Wf3 = (const float*)d_in[7];
    const float* Wd3 = (const float*)d_in[8];
    const float* Wf4 = (const float*)d_in[9];
    const float* Wd4 = (const float*)d_in[10];
    float* out = (float*)d_out;

    float* feat = nullptr;
    cudaGetSymbolAddress((void**)&feat, g_feat);

    cudaFuncSetAttribute(vn_edge_kernel<42, 85>,
                         cudaFuncAttributeMaxDynamicSharedMemorySize, (int)vn_smem(42, 85));

    const int XXG  = BATCH * NPT / 256;      // 32
    const int KNNG = BATCH * (NPT / 8);      // 1024

    // layer 0 : C=1, D=3, out=21 -> feat[0:21)
    xx_kernel <<<XXG, 256>>>(x, 1, 0, 3);
    knn_kernel<<<KNNG, 256>>>(x, 1, 0, 3);
    vn_edge_kernel<1, 21><<<1184, 256, vn_smem(1, 21)>>>(x, 1, 0, Wf0, Wd0, 0);

    // layer 1 : C=21, D=63, out=21 -> feat[21:42)
    xx_kernel <<<XXG, 256>>>(feat, CTOT, 0, 63);
    knn_kernel<<<KNNG, 256>>>(feat, CTOT, 0, 63);
    vn_edge_kernel<21, 21><<<1184, 256, vn_smem(21, 21)>>>(feat, CTOT, 0, Wf1, Wd1, 21);

    // layer 2 : C=21, D=63, out=42 -> feat[42:84)
    xx_kernel <<<XXG, 256>>>(feat, CTOT, 21, 63);
    knn_kernel<<<KNNG, 256>>>(feat, CTOT, 21, 63);
    vn_edge_kernel<21, 42><<<1184, 256, vn_smem(21, 42)>>>(feat, CTOT, 21, Wf2, Wd2, 42);

    // layer 3 : C=42, D=126, out=85 -> feat[84:169)
    xx_kernel <<<XXG, 256>>>(feat, CTOT, 42, 126);
    knn_kernel<<<KNNG, 256>>>(feat, CTOT, 42, 126);
    vn_edge_kernel<42, 85><<<444, 256, vn_smem(42, 85)>>>(feat, CTOT, 42, Wf3, Wd3, 84);

    // final VN layer on concat [0:169) + mean over N
    final_kernel<<<BATCH * 31, 256>>>(Wf4, Wd4, out);
}

// round 2
// speedup vs baseline: 1.9103x; 1.9103x over previous
#include <cuda_runtime.h>
#include <cfloat>

#define BATCH 8
#define NPT   1024
#define KNN   20
#define EPSV  1e-6f
#define CTOT  169   // 21+21+42+85 concat channels

typedef unsigned long long u64;

// ---- packed f32x2 helpers (sm_10x FFMA2) ----
__device__ __forceinline__ u64 pk2(float lo, float hi) {
    u64 r; asm("mov.b64 %0,{%1,%2};" : "=l"(r) : "f"(lo), "f"(hi)); return r;
}
__device__ __forceinline__ void fma2(u64& d, u64 a, u64 b) {
    asm("fma.rn.f32x2 %0,%1,%2,%0;" : "+l"(d) : "l"(a), "l"(b));
}
__device__ __forceinline__ float2 up2(u64 v) {
    float2 r; asm("mov.b64 {%0,%1},%2;" : "=f"(r.x), "=f"(r.y) : "l"(v)); return r;
}

// -------- scratch (no allocations allowed) --------
__device__ float g_feat[BATCH * CTOT * 3 * NPT];   // [B][169][3][N]
__device__ float g_xx[BATCH * NPT];
__device__ int   g_idx[BATCH * NPT * KNN];

// ================= squared norms =================
__global__ void xx_kernel(const float* __restrict__ cur, int Ctot, int coff, int D)
{
    int idx = blockIdx.x * blockDim.x + threadIdx.x;
    if (idx >= BATCH * NPT) return;
    int b = idx >> 10, n = idx & (NPT - 1);
    const float* base = cur + (size_t)(b * Ctot + coff) * 3 * NPT;
    float s = 0.f;
    for (int f = 0; f < D; f++) { float v = base[f * NPT + n]; s += v * v; }
    g_xx[idx] = s;
}

// ================= knn + top-k =================
// block handles 8 query points of one batch; warp w does top-k for row w
__global__ void knn_kernel(const float* __restrict__ cur, int Ctot, int coff, int D)
{
    const int TI = 8;
    __shared__ u64   sxp[128][4];     // packed query features {q0,q1}{q2,q3}{q4,q5}{q6,q7}
    __shared__ float sxxi[TI];
    __shared__ float sdist[TI][NPT];

    int blk = blockIdx.x;
    int b   = blk / (NPT / TI);
    int i0  = (blk % (NPT / TI)) * TI;
    int tid = threadIdx.x;
    const float* base = cur + (size_t)(b * Ctot + coff) * 3 * NPT;

    for (int f = tid; f < D; f += blockDim.x) {
        float q[TI];
        #pragma unroll
        for (int ii = 0; ii < TI; ii++) q[ii] = base[f * NPT + i0 + ii];
        sxp[f][0] = pk2(q[0], q[1]);
        sxp[f][1] = pk2(q[2], q[3]);
        sxp[f][2] = pk2(q[4], q[5]);
        sxp[f][3] = pk2(q[6], q[7]);
    }
    if (tid < TI) sxxi[tid] = g_xx[b * NPT + i0 + tid];
    __syncthreads();

    for (int j = tid; j < NPT; j += blockDim.x) {
        u64 a0 = 0ull, a1 = 0ull, a2 = 0ull, a3 = 0ull;
        for (int f = 0; f < D; f++) {
            float xv = base[f * NPT + j];
            u64 xp = pk2(xv, xv);
            fma2(a0, sxp[f][0], xp);
            fma2(a1, sxp[f][1], xp);
            fma2(a2, sxp[f][2], xp);
            fma2(a3, sxp[f][3], xp);
        }
        float xxj = g_xx[b * NPT + j];
        float2 v0 = up2(a0), v1 = up2(a1), v2 = up2(a2), v3 = up2(a3);
        sdist[0][j] = 2.f * v0.x - sxxi[0] - xxj;
        sdist[1][j] = 2.f * v0.y - sxxi[1] - xxj;
        sdist[2][j] = 2.f * v1.x - sxxi[2] - xxj;
        sdist[3][j] = 2.f * v1.y - sxxi[3] - xxj;
        sdist[4][j] = 2.f * v2.x - sxxi[4] - xxj;
        sdist[5][j] = 2.f * v2.y - sxxi[5] - xxj;
        sdist[6][j] = 2.f * v3.x - sxxi[6] - xxj;
        sdist[7][j] = 2.f * v3.y - sxxi[7] - xxj;
    }
    __syncthreads();

    int w = tid >> 5, lane = tid & 31;
    if (w < TI) {
        float* row = sdist[w];
        int ob = (b * NPT + i0 + w) * KNN;
        for (int it = 0; it < KNN; it++) {
            float best = -FLT_MAX; int bi = NPT;
            for (int j = lane; j < NPT; j += 32) {
                float v = row[j];
                if (v > best) { best = v; bi = j; }   // ascending j => smallest idx on ties
            }
            #pragma unroll
            for (int s = 16; s; s >>= 1) {
                float ov = __shfl_down_sync(0xffffffffu, best, s);
                int   oi = __shfl_down_sync(0xffffffffu, bi,   s);
                if (ov > best || (ov == best && oi < bi)) { best = ov; bi = oi; }
            }
            bi = __shfl_sync(0xffffffffu, bi, 0);
            if (lane == 0) g_idx[ob + it] = bi;
            row[bi] = -FLT_MAX;
            __syncwarp();
        }
    }
}

// ========== fused graph-feature + VN linear-leakyReLU + mean over k ==========
// Register-blocked: thread <-> (o-group of OB outputs, j-tile of JB neighbors).
// p_{o,j} = sum_c WfL[o,c]*diff_{c,j} + pconst[o];  pconst = WfR x_n (same for d).
template <int CIN, int COUT, int OB, int JB>
__global__ void vn_edge2(const float* __restrict__ cur, int Ctot, int coff,
                         const float* __restrict__ Wf, const float* __restrict__ Wd,
                         int ooff)
{
    const int IN2  = 2 * CIN;
    const int NJT  = KNN / JB;
    const int OGRP = COUT / OB;       // exact division by construction
    const int ACT  = OGRP * NJT;

    extern __shared__ float sm[];
    float2* sW    = (float2*)sm;                   // [CIN][COUT] left halves {wf,wd}
    float2* sWr   = sW  + CIN * COUT;              // [CIN][COUT] right halves {wf,wd}
    float4* sdif  = (float4*)(sWr + CIN * COUT);   // [CIN][KNN]
    float*  sxn   = (float*)(sdif + CIN * KNN);    // [3*CIN]
    float*  spc   = sxn + 3 * CIN;                 // [3*COUT]
    float*  sdc   = spc + 3 * COUT;                // [3*COUT]
    float*  spart = sdc + 3 * COUT;                // [COUT][NJT][3]
    int*    sidx  = (int*)(spart + COUT * NJT * 3);

    int tid = threadIdx.x;
    for (int t = tid; t < CIN * COUT; t += blockDim.x) {
        int c = t / COUT, o = t - c * COUT;
        sW [t] = make_float2(Wf[o * IN2 + c],       Wd[o * IN2 + c]);
        sWr[t] = make_float2(Wf[o * IN2 + CIN + c], Wd[o * IN2 + CIN + c]);
    }
    __syncthreads();

    for (int pt = blockIdx.x; pt < BATCH * NPT; pt += gridDim.x) {
        int b = pt >> 10, n = pt & (NPT - 1);
        const float* base = cur + (size_t)(b * Ctot + coff) * 3 * NPT;

        for (int t = tid; t < 3 * CIN; t += blockDim.x) sxn[t] = base[t * NPT + n];
        if (tid < KNN) sidx[tid] = g_idx[pt * KNN + tid];
        __syncthreads();

        // diffs into shared
        for (int t = tid; t < CIN * KNN; t += blockDim.x) {
            int c = t / KNN;
            int nj = sidx[t - c * KNN];
            float4 dv;
            dv.x = base[(c * 3 + 0) * NPT + nj] - sxn[c * 3 + 0];
            dv.y = base[(c * 3 + 1) * NPT + nj] - sxn[c * 3 + 1];
            dv.z = base[(c * 3 + 2) * NPT + nj] - sxn[c * 3 + 2];
            dv.w = 0.f;
            sdif[t] = dv;
        }
        // j-independent const parts
        for (int o = tid; o < COUT; o += blockDim.x) {
            float p0 = 0, p1 = 0, p2 = 0, q0 = 0, q1 = 0, q2 = 0;
            for (int c = 0; c < CIN; c++) {
                float2 w = sWr[c * COUT + o];
                float x0 = sxn[3 * c], x1 = sxn[3 * c + 1], x2 = sxn[3 * c + 2];
                p0 += w.x * x0; p1 += w.x * x1; p2 += w.x * x2;
                q0 += w.y * x0; q1 += w.y * x1; q2 += w.y * x2;
            }
            spc[3 * o] = p0; spc[3 * o + 1] = p1; spc[3 * o + 2] = p2;
            sdc[3 * o] = q0; sdc[3 * o + 1] = q1; sdc[3 * o + 2] = q2;
        }
        __syncthreads();

        if (tid < ACT) {
            int og = tid / NJT, jt = tid - og * NJT;
            int o0 = og * OB, j0 = jt * JB;
            u64 pxy[OB][JB]; float pz[OB][JB];
            u64 dxy[OB][JB]; float dz[OB][JB];
            #pragma unroll
            for (int ob = 0; ob < OB; ob++) {
                int o = o0 + ob;
                u64 pc = pk2(spc[3 * o], spc[3 * o + 1]); float pcz = spc[3 * o + 2];
                u64 dc = pk2(sdc[3 * o], sdc[3 * o + 1]); float dcz = sdc[3 * o + 2];
                #pragma unroll
                for (int jj = 0; jj < JB; jj++) {
                    pxy[ob][jj] = pc; pz[ob][jj] = pcz;
                    dxy[ob][jj] = dc; dz[ob][jj] = dcz;
                }
            }
            for (int c = 0; c < CIN; c++) {
                float2 w[OB]; u64 wf2[OB], wd2[OB];
                #pragma unroll
                for (int ob = 0; ob < OB; ob++) {
                    w[ob] = sW[c * COUT + o0 + ob];
                    wf2[ob] = pk2(w[ob].x, w[ob].x);
                    wd2[ob] = pk2(w[ob].y, w[ob].y);
                }
                #pragma unroll
                for (int jj = 0; jj < JB; jj++) {
                    float4 dv = sdif[c * KNN + j0 + jj];
                    u64 dxyp = pk2(dv.x, dv.y);
                    #pragma unroll
                    for (int ob = 0; ob < OB; ob++) {
                        fma2(pxy[ob][jj], wf2[ob], dxyp);
                        pz[ob][jj] += w[ob].x * dv.z;
                        fma2(dxy[ob][jj], wd2[ob], dxyp);
                        dz[ob][jj] += w[ob].y * dv.z;
                    }
                }
            }
            #pragma unroll
            for (int ob = 0; ob < OB; ob++) {
                float a0 = 0, a1 = 0, a2 = 0;
                #pragma unroll
                for (int jj = 0; jj < JB; jj++) {
                    float2 pv = up2(pxy[ob][jj]);
                    float2 dvv = up2(dxy[ob][jj]);
                    float P0 = pv.x, P1 = pv.y, P2 = pz[ob][jj];
                    float D0 = dvv.x, D1 = dvv.y, D2 = dz[ob][jj];
                    float dot = P0 * D0 + P1 * D1 + P2 * D2;
                    if (dot >= 0.f) { a0 += P0; a1 += P1; a2 += P2; }
                    else {
                        float s = 0.8f * dot / (D0 * D0 + D1 * D1 + D2 * D2 + EPSV);
                        a0 += P0 - s * D0; a1 += P1 - s * D1; a2 += P2 - s * D2;
                    }
                }
                float* pp = &spart[((o0 + ob) * NJT + jt) * 3];
                pp[0] = a0; pp[1] = a1; pp[2] = a2;
            }
        }
        __syncthreads();

        // reduce over j-tiles and write (deterministic order)
        for (int t = tid; t < COUT * 3; t += blockDim.x) {
            int o = t / 3, k = t - o * 3;
            float s = 0.f;
            for (int jt = 0; jt < NJT; jt++) s += spart[(o * NJT + jt) * 3 + k];
            g_feat[(((size_t)b * CTOT + ooff + o) * 3 + k) * NPT + n] = s * (1.f / KNN);
        }
        __syncthreads();
    }
}

// ========== final VN layer (no graph) + mean over N ==========
__global__ void final_kernel(const float* __restrict__ Wf, const float* __restrict__ Wd,
                             float* __restrict__ out)
{
    const int OT = 11;               // 341 = 31 * 11
    const int CI = CTOT;
    __shared__ float sWf[OT * CI];
    __shared__ float sWd[CI];
    __shared__ float sacc[OT * 3];
    int b  = blockIdx.x / 31;
    int o0 = (blockIdx.x % 31) * OT;
    int tid = threadIdx.x;

    for (int t = tid; t < OT * CI; t += blockDim.x) {
        int o = t / CI, c = t - o * CI;
        sWf[t] = Wf[(o0 + o) * CI + c];
    }
    for (int t = tid; t < CI; t += blockDim.x) sWd[t] = Wd[t];
    if (tid < OT * 3) sacc[tid] = 0.f;
    __syncthreads();

    float sum[OT][3];
    #pragma unroll
    for (int o = 0; o < OT; o++) { sum[o][0] = sum[o][1] = sum[o][2] = 0.f; }

    const float* base = g_feat + (size_t)b * CTOT * 3 * NPT;
    for (int n = tid; n < NPT; n += blockDim.x) {
        float p[OT][3];
        #pragma unroll
        for (int o = 0; o < OT; o++) { p[o][0] = p[o][1] = p[o][2] = 0.f; }
        float d0 = 0, d1 = 0, d2 = 0;
        for (int c = 0; c < CI; c++) {
            float x0 = base[(c * 3 + 0) * NPT + n];
            float x1 = base[(c * 3 + 1) * NPT + n];
            float x2 = base[(c * 3 + 2) * NPT + n];
            float wd = sWd[c];
            d0 += wd * x0; d1 += wd * x1; d2 += wd * x2;
            #pragma unroll
            for (int o = 0; o < OT; o++) {
                float w = sWf[o * CI + c];
                p[o][0] += w * x0; p[o][1] += w * x1; p[o][2] += w * x2;
            }
        }
        float inv = 1.f / (d0 * d0 + d1 * d1 + d2 * d2 + EPSV);
        #pragma unroll
        for (int o = 0; o < OT; o++) {
            float dot = p[o][0] * d0 + p[o][1] * d1 + p[o][2] * d2;
            if (dot >= 0.f) {
                sum[o][0] += p[o][0]; sum[o][1] += p[o][1]; sum[o][2] += p[o][2];
            } else {
                float s = 0.8f * dot * inv;
                sum[o][0] += p[o][0] - s * d0;
                sum[o][1] += p[o][1] - s * d1;
                sum[o][2] += p[o][2] - s * d2;
            }
        }
    }
    #pragma unroll
    for (int o = 0; o < OT; o++)
        #pragma unroll
        for (int dd = 0; dd < 3; dd++) {
            float v = sum[o][dd];
            #pragma unroll
            for (int s = 16; s; s >>= 1) v += __shfl_down_sync(0xffffffffu, v, s);
            if ((tid & 31) == 0) atomicAdd(&sacc[o * 3 + dd], v);
        }
    __syncthreads();
    if (tid < OT * 3) out[b * 341 * 3 + o0 * 3 + tid] = sacc[tid] * (1.f / NPT);
}

// ================= launch =================
static constexpr size_t vn_smem(int CIN, int COUT, int NJT)
{
    return (size_t)(4 * CIN * COUT + 4 * CIN * KNN + 3 * CIN + 6 * COUT
                    + 3 * COUT * NJT + KNN) * 4;
}

extern "C" void kernel_launch(void* const* d_in, const int* in_sizes, int n_in,
                              void* d_out, int out_size)
{
    const float* x   = (const float*)d_in[0];
    const float* Wf0 = (const float*)d_in[1];
    const float* Wd0 = (const float*)d_in[2];
    const float* Wf1 = (const float*)d_in[3];
    const float* Wd1 = (const float*)d_in[4];
    const float* Wf2 = (const float*)d_in[5];
    const float* Wd2 = (const float*)d_in[6];
    const float* Wf3 = (const float*)d_in[7];
    const float* Wd3 = (const float*)d_in[8];
    const float* Wf4 = (const float*)d_in[9];
    const float* Wd4 = (const float*)d_in[10];
    float* out = (float*)d_out;

    float* feat = nullptr;
    cudaGetSymbolAddress((void**)&feat, g_feat);

    static bool attr_done = false;
    if (!attr_done) {
        cudaFuncSetAttribute(vn_edge2<42, 85, 5, 2>,
                             cudaFuncAttributeMaxDynamicSharedMemorySize,
                             (int)vn_smem(42, 85, 10));
        attr_done = true;
    }

    const int XXG  = BATCH * NPT / 256;      // 32
    const int KNNG = BATCH * (NPT / 8);      // 1024

    // layer 0 : C=1, D=3, out=21 -> feat[0:21)
    xx_kernel <<<XXG, 256>>>(x, 1, 0, 3);
    knn_kernel<<<KNNG, 256>>>(x, 1, 0, 3);
    vn_edge2<1, 21, 1, 2><<<1184, 224, vn_smem(1, 21, 10)>>>(x, 1, 0, Wf0, Wd0, 0);

    // layer 1 : C=21, D=63, out=21 -> feat[21:42)
    xx_kernel <<<XXG, 256>>>(feat, CTOT, 0, 63);
    knn_kernel<<<KNNG, 256>>>(feat, CTOT, 0, 63);
    vn_edge2<21, 21, 1, 2><<<1184, 224, vn_smem(21, 21, 10)>>>(feat, CTOT, 0, Wf1, Wd1, 21);

    // layer 2 : C=21, D=63, out=42 -> feat[42:84)
    xx_kernel <<<XXG, 256>>>(feat, CTOT, 21, 63);
    knn_kernel<<<KNNG, 256>>>(feat, CTOT, 21, 63);
    vn_edge2<21, 42, 2, 2><<<1184, 224, vn_smem(21, 42, 10)>>>(feat, CTOT, 21, Wf2, Wd2, 42);

    // layer 3 : C=42, D=126, out=85 -> feat[84:169)
    xx_kernel <<<XXG, 256>>>(feat, CTOT, 42, 126);
    knn_kernel<<<KNNG, 256>>>(feat, CTOT, 42, 126);
    vn_edge2<42, 85, 5, 2><<<296, 192, vn_smem(42, 85, 10)>>>(feat, CTOT, 42, Wf3, Wd3, 84);

    // final VN layer on concat [0:169) + mean over N
    final_kernel<<<BATCH * 31, 256>>>(Wf4, Wd4, out);
}

// round 3
// speedup vs baseline: 2.8874x; 1.5115x over previous
#include <cuda_runtime.h>
#include <cfloat>

#define BATCH 8
#define NPT   1024
#define KNN   20
#define EPSV  1e-6f
#define CTOT  169   // 21+21+42+85 concat channels
#define MAXCOUT 85

typedef unsigned long long u64;

// ---- packed f32x2 helpers (sm_10x FFMA2) ----
__device__ __forceinline__ u64 pk2(float lo, float hi) {
    u64 r; asm("mov.b64 %0,{%1,%2};" : "=l"(r) : "f"(lo), "f"(hi)); return r;
}
__device__ __forceinline__ void fma2(u64& d, u64 a, u64 b) {
    asm("fma.rn.f32x2 %0,%1,%2,%0;" : "+l"(d) : "l"(a), "l"(b));
}
__device__ __forceinline__ float2 up2(u64 v) {
    float2 r; asm("mov.b64 {%0,%1},%2;" : "=f"(r.x), "=f"(r.y) : "l"(v)); return r;
}

// -------- scratch (no allocations allowed) --------
__device__ float  g_feat[BATCH * CTOT * 3 * NPT];        // [B][169][3][N]
__device__ float  g_xx[BATCH * NPT];
__device__ int    g_idx[BATCH * NPT * KNN];
__device__ float2 g_y  [BATCH * NPT * MAXCOUT * 3];      // [pt][o][f] {yf,yd}
__device__ float2 g_cmb[BATCH * NPT * MAXCOUT * 3];      // [pt][o][f] {pc-yf, dc-yd}

// ================= squared norms =================
__global__ void xx_kernel(const float* __restrict__ cur, int Ctot, int coff, int D)
{
    int idx = blockIdx.x * blockDim.x + threadIdx.x;
    if (idx >= BATCH * NPT) return;
    int b = idx >> 10, n = idx & (NPT - 1);
    const float* base = cur + (size_t)(b * Ctot + coff) * 3 * NPT;
    float s = 0.f;
    for (int f = 0; f < D; f++) { float v = base[f * NPT + n]; s += v * v; }
    g_xx[idx] = s;
}

// ================= knn + top-k =================
__global__ void knn_kernel(const float* __restrict__ cur, int Ctot, int coff, int D)
{
    const int TI = 8;
    __shared__ u64   sxp[128][4];
    __shared__ float sxxi[TI];
    __shared__ float sdist[TI][NPT];

    int blk = blockIdx.x;
    int b   = blk / (NPT / TI);
    int i0  = (blk % (NPT / TI)) * TI;
    int tid = threadIdx.x;
    const float* base = cur + (size_t)(b * Ctot + coff) * 3 * NPT;

    for (int f = tid; f < D; f += blockDim.x) {
        float q[TI];
        #pragma unroll
        for (int ii = 0; ii < TI; ii++) q[ii] = base[f * NPT + i0 + ii];
        sxp[f][0] = pk2(q[0], q[1]);
        sxp[f][1] = pk2(q[2], q[3]);
        sxp[f][2] = pk2(q[4], q[5]);
        sxp[f][3] = pk2(q[6], q[7]);
    }
    if (tid < TI) sxxi[tid] = g_xx[b * NPT + i0 + tid];
    __syncthreads();

    for (int j = tid; j < NPT; j += blockDim.x) {
        u64 a0 = 0ull, a1 = 0ull, a2 = 0ull, a3 = 0ull;
        for (int f = 0; f < D; f++) {
            float xv = base[f * NPT + j];
            u64 xp = pk2(xv, xv);
            fma2(a0, sxp[f][0], xp);
            fma2(a1, sxp[f][1], xp);
            fma2(a2, sxp[f][2], xp);
            fma2(a3, sxp[f][3], xp);
        }
        float xxj = g_xx[b * NPT + j];
        float2 v0 = up2(a0), v1 = up2(a1), v2 = up2(a2), v3 = up2(a3);
        sdist[0][j] = 2.f * v0.x - sxxi[0] - xxj;
        sdist[1][j] = 2.f * v0.y - sxxi[1] - xxj;
        sdist[2][j] = 2.f * v1.x - sxxi[2] - xxj;
        sdist[3][j] = 2.f * v1.y - sxxi[3] - xxj;
        sdist[4][j] = 2.f * v2.x - sxxi[4] - xxj;
        sdist[5][j] = 2.f * v2.y - sxxi[5] - xxj;
        sdist[6][j] = 2.f * v3.x - sxxi[6] - xxj;
        sdist[7][j] = 2.f * v3.y - sxxi[7] - xxj;
    }
    __syncthreads();

    int w = tid >> 5, lane = tid & 31;
    if (w < TI) {
        float* row = sdist[w];
        int ob = (b * NPT + i0 + w) * KNN;
        for (int it = 0; it < KNN; it++) {
            float best = -FLT_MAX; int bi = NPT;
            for (int j = lane; j < NPT; j += 32) {
                float v = row[j];
                if (v > best) { best = v; bi = j; }
            }
            #pragma unroll
            for (int s = 16; s; s >>= 1) {
                float ov = __shfl_down_sync(0xffffffffu, best, s);
                int   oi = __shfl_down_sync(0xffffffffu, bi,   s);
                if (ov > best || (ov == best && oi < bi)) { best = ov; bi = oi; }
            }
            bi = __shfl_sync(0xffffffffu, bi, 0);
            if (lane == 0) g_idx[ob + it] = bi;
            row[bi] = -FLT_MAX;
            __syncwarp();
        }
    }
}

// ================= per-point linear maps =================
// y = Wf_L x (paired with Wd_L), cmb = (Wf_R x - y) paired with (Wd_R x - yd)
template <int CIN, int COUT>
__global__ void ymap_kernel(const float* __restrict__ cur, int Ctot, int coff,
                            const float* __restrict__ Wf, const float* __restrict__ Wd)
{
    const int IN2 = 2 * CIN;
    extern __shared__ float sm[];
    float4* sW = (float4*)sm;                 // [CIN][COUT] {wfL,wdL,wfR,wdR}
    float*  sx = sm + 4 * CIN * COUT;         // [3*CIN][32]

    int tid = threadIdx.x;
    int nn = tid & 31, og = tid >> 5;         // 8 o-groups
    int pt0 = blockIdx.x * 32;
    int b = pt0 >> 10, n0 = pt0 & (NPT - 1);
    const float* base = cur + (size_t)(b * Ctot + coff) * 3 * NPT;

    for (int t = tid; t < CIN * COUT; t += blockDim.x) {
        int c = t / COUT, o = t - c * COUT;
        sW[t] = make_float4(Wf[o * IN2 + c], Wd[o * IN2 + c],
                            Wf[o * IN2 + CIN + c], Wd[o * IN2 + CIN + c]);
    }
    for (int t = tid; t < 3 * CIN * 32; t += blockDim.x) {
        int row = t >> 5, col = t & 31;
        sx[t] = base[row * NPT + n0 + col];
    }
    __syncthreads();

    int pt = pt0 + nn;
    for (int o = og; o < COUT; o += 8) {
        u64 accL0 = 0ull, accL1 = 0ull, accL2 = 0ull;
        u64 accR0 = 0ull, accR1 = 0ull, accR2 = 0ull;
        for (int c = 0; c < CIN; c++) {
            float4 w = sW[c * COUT + o];
            u64 wl = pk2(w.x, w.y);
            u64 wr = pk2(w.z, w.w);
            float x0 = sx[(c * 3 + 0) * 32 + nn];
            float x1 = sx[(c * 3 + 1) * 32 + nn];
            float x2 = sx[(c * 3 + 2) * 32 + nn];
            u64 p0 = pk2(x0, x0), p1 = pk2(x1, x1), p2 = pk2(x2, x2);
            fma2(accL0, wl, p0); fma2(accR0, wr, p0);
            fma2(accL1, wl, p1); fma2(accR1, wr, p1);
            fma2(accL2, wl, p2); fma2(accR2, wr, p2);
        }
        float2* yo = g_y   + ((size_t)pt * COUT + o) * 3;
        float2* co = g_cmb + ((size_t)pt * COUT + o) * 3;
        float2 l0 = up2(accL0), l1 = up2(accL1), l2 = up2(accL2);
        float2 r0 = up2(accR0), r1 = up2(accR1), r2 = up2(accR2);
        yo[0] = l0; yo[1] = l1; yo[2] = l2;
        co[0] = make_float2(r0.x - l0.x, r0.y - l0.y);
        co[1] = make_float2(r1.x - l1.x, r1.y - l1.y);
        co[2] = make_float2(r2.x - l2.x, r2.y - l2.y);
    }
}

// ================= gather + leaky combine + mean over k =================
// p_{o,j} = y(nj,o) + cmb(n,o);  leaky;  mean over j
template <int COUT, int P, int TPB>
__global__ void pair_kernel(int ooff)
{
    __shared__ int sidx[P][KNN];
    int tid = threadIdx.x;
    int pt0 = blockIdx.x * P;

    for (int t = tid; t < P * KNN; t += TPB)
        sidx[t / KNN][t % KNN] = g_idx[(pt0 + t / KNN) * KNN + (t % KNN)];
    __syncthreads();

    int ln = tid / COUT, o = tid - ln * COUT;
    if (ln >= P) return;
    int pt = pt0 + ln;
    int b = pt >> 10, n = pt & (NPT - 1);

    const float2* cmb = g_cmb + ((size_t)pt * COUT + o) * 3;
    float2 c0 = cmb[0], c1 = cmb[1], c2 = cmb[2];

    float a0 = 0.f, a1 = 0.f, a2 = 0.f;
    #pragma unroll 4
    for (int j = 0; j < KNN; j++) {
        int nj = sidx[ln][j];
        const float2* y = g_y + (((size_t)(b << 10) + nj) * COUT + o) * 3;
        float2 y0 = y[0], y1 = y[1], y2 = y[2];
        float P0 = y0.x + c0.x, D0 = y0.y + c0.y;
        float P1 = y1.x + c1.x, D1 = y1.y + c1.y;
        float P2 = y2.x + c2.x, D2 = y2.y + c2.y;
        float dot = P0 * D0 + P1 * D1 + P2 * D2;
        if (dot >= 0.f) { a0 += P0; a1 += P1; a2 += P2; }
        else {
            float s = dot / (D0 * D0 + D1 * D1 + D2 * D2 + EPSV);
            a0 += 0.2f * P0 + 0.8f * (P0 - s * D0);
            a1 += 0.2f * P1 + 0.8f * (P1 - s * D1);
            a2 += 0.2f * P2 + 0.8f * (P2 - s * D2);
        }
    }
    const float invK = 1.f / KNN;
    float* fo = g_feat + (((size_t)b * CTOT + ooff + o) * 3) * NPT + n;
    fo[0 * NPT] = a0 * invK;
    fo[1 * NPT] = a1 * invK;
    fo[2 * NPT] = a2 * invK;
}

// ========== final VN layer (no graph) + mean over N ==========
__global__ void final_kernel(const float* __restrict__ Wf, const float* __restrict__ Wd,
                             float* __restrict__ out)
{
    const int OT = 11;               // 341 = 31 * 11
    const int CI = CTOT;
    __shared__ float sWf[OT * CI];
    __shared__ float sWd[CI];
    __shared__ float sacc[OT * 3];
    int b  = blockIdx.x / 31;
    int o0 = (blockIdx.x % 31) * OT;
    int tid = threadIdx.x;

    for (int t = tid; t < OT * CI; t += blockDim.x) {
        int o = t / CI, c = t - o * CI;
        sWf[t] = Wf[(o0 + o) * CI + c];
    }
    for (int t = tid; t < CI; t += blockDim.x) sWd[t] = Wd[t];
    if (tid < OT * 3) sacc[tid] = 0.f;
    __syncthreads();

    float sum[OT][3];
    #pragma unroll
    for (int o = 0; o < OT; o++) { sum[o][0] = sum[o][1] = sum[o][2] = 0.f; }

    const float* base = g_feat + (size_t)b * CTOT * 3 * NPT;
    for (int n = tid; n < NPT; n += blockDim.x) {
        float p[OT][3];
        #pragma unroll
        for (int o = 0; o < OT; o++) { p[o][0] = p[o][1] = p[o][2] = 0.f; }
        float d0 = 0, d1 = 0, d2 = 0;
        for (int c = 0; c < CI; c++) {
            float x0 = base[(c * 3 + 0) * NPT + n];
            float x1 = base[(c * 3 + 1) * NPT + n];
            float x2 = base[(c * 3 + 2) * NPT + n];
            float wd = sWd[c];
            d0 += wd * x0; d1 += wd * x1; d2 += wd * x2;
            #pragma unroll
            for (int o = 0; o < OT; o++) {
                float w = sWf[o * CI + c];
                p[o][0] += w * x0; p[o][1] += w * x1; p[o][2] += w * x2;
            }
        }
        float inv = 1.f / (d0 * d0 + d1 * d1 + d2 * d2 + EPSV);
        #pragma unroll
        for (int o = 0; o < OT; o++) {
            float dot = p[o][0] * d0 + p[o][1] * d1 + p[o][2] * d2;
            if (dot >= 0.f) {
                sum[o][0] += p[o][0]; sum[o][1] += p[o][1]; sum[o][2] += p[o][2];
            } else {
                float s = dot * inv;
                sum[o][0] += 0.2f * p[o][0] + 0.8f * (p[o][0] - s * d0);
                sum[o][1] += 0.2f * p[o][1] + 0.8f * (p[o][1] - s * d1);
                sum[o][2] += 0.2f * p[o][2] + 0.8f * (p[o][2] - s * d2);
            }
        }
    }
    #pragma unroll
    for (int o = 0; o < OT; o++)
        #pragma unroll
        for (int dd = 0; dd < 3; dd++) {
            float v = sum[o][dd];
            #pragma unroll
            for (int s = 16; s; s >>= 1) v += __shfl_down_sync(0xffffffffu, v, s);
            if ((tid & 31) == 0) atomicAdd(&sacc[o * 3 + dd], v);
        }
    __syncthreads();
    if (tid < OT * 3) out[b * 341 * 3 + o0 * 3 + tid] = sacc[tid] * (1.f / NPT);
}

// ================= launch =================
static constexpr size_t ymap_smem(int CIN, int COUT)
{
    return (size_t)(4 * CIN * COUT + 3 * CIN * 32) * 4;
}

extern "C" void kernel_launch(void* const* d_in, const int* in_sizes, int n_in,
                              void* d_out, int out_size)
{
    const float* x   = (const float*)d_in[0];
    const float* Wf0 = (const float*)d_in[1];
    const float* Wd0 = (const float*)d_in[2];
    const float* Wf1 = (const float*)d_in[3];
    const float* Wd1 = (const float*)d_in[4];
    const float* Wf2 = (const float*)d_in[5];
    const float* Wd2 = (const float*)d_in[6];
    const float* Wf3 = (const float*)d_in[7];
    const float* Wd3 = (const float*)d_in[8];
    const float* Wf4 = (const float*)d_in[9];
    const float* Wd4 = (const float*)d_in[10];
    float* out = (float*)d_out;

    float* feat = nullptr;
    cudaGetSymbolAddress((void**)&feat, g_feat);

    static bool attr_done = false;
    if (!attr_done) {
        cudaFuncSetAttribute(ymap_kernel<42, 85>,
                             cudaFuncAttributeMaxDynamicSharedMemorySize,
                             (int)ymap_smem(42, 85));
        attr_done = true;
    }

    const int XXG = BATCH * NPT / 256;       // 32
    const int KNNG = BATCH * (NPT / 8);      // 1024
    const int YG  = BATCH * NPT / 32;        // 256

    // layer 0 : CIN=1, D=3, out=21 -> feat[0:21)
    xx_kernel <<<XXG, 256>>>(x, 1, 0, 3);
    knn_kernel<<<KNNG, 256>>>(x, 1, 0, 3);
    ymap_kernel<1, 21><<<YG, 256, ymap_smem(1, 21)>>>(x, 1, 0, Wf0, Wd0);
    pair_kernel<21, 8, 192><<<BATCH * NPT / 8, 192>>>(0);

    // layer 1 : CIN=21, D=63, out=21 -> feat[21:42)
    xx_kernel <<<XXG, 256>>>(feat, CTOT, 0, 63);
    knn_kernel<<<KNNG, 256>>>(feat, CTOT, 0, 63);
    ymap_kernel<21, 21><<<YG, 256, ymap_smem(21, 21)>>>(feat, CTOT, 0, Wf1, Wd1);
    pair_kernel<21, 8, 192><<<BATCH * NPT / 8, 192>>>(21);

    // layer 2 : CIN=21, D=63, out=42 -> feat[42:84)
    xx_kernel <<<XXG, 256>>>(feat, CTOT, 21, 63);
    knn_kernel<<<KNNG, 256>>>(feat, CTOT, 21, 63);
    ymap_kernel<21, 42><<<YG, 256, ymap_smem(21, 42)>>>(feat, CTOT, 21, Wf2, Wd2);
    pair_kernel<42, 4, 192><<<BATCH * NPT / 4, 192>>>(42);

    // layer 3 : CIN=42, D=126, out=85 -> feat[84:169)
    xx_kernel <<<XXG, 256>>>(feat, CTOT, 42, 126);
    knn_kernel<<<KNNG, 256>>>(feat, CTOT, 42, 126);
    ymap_kernel<42, 85><<<YG, 256, ymap_smem(42, 85)>>>(feat, CTOT, 42, Wf3, Wd3);
    pair_kernel<85, 2, 192><<<BATCH * NPT / 2, 192>>>(84);

    // final VN layer on concat [0:169) + mean over N
    final_kernel<<<BATCH * 31, 256>>>(Wf4, Wd4, out);
}

// round 4
// speedup vs baseline: 3.3834x; 1.1718x over previous
#include <cuda_runtime.h>
#include <cfloat>

#define BATCH 8
#define NPT   1024
#define KNN   20
#define EPSV  1e-6f
#define CTOT  169   // 21+21+42+85 concat channels
#define MAXCOUT 85
#define TOTPT (BATCH * NPT)

typedef unsigned long long u64;

// ---- packed f32x2 helpers (sm_10x FFMA2) ----
__device__ __forceinline__ u64 pk2(float lo, float hi) {
    u64 r; asm("mov.b64 %0,{%1,%2};" : "=l"(r) : "f"(lo), "f"(hi)); return r;
}
__device__ __forceinline__ void fma2(u64& d, u64 a, u64 b) {
    asm("fma.rn.f32x2 %0,%1,%2,%0;" : "+l"(d) : "l"(a), "l"(b));
}
__device__ __forceinline__ float2 up2(u64 v) {
    float2 r; asm("mov.b64 {%0,%1},%2;" : "=f"(r.x), "=f"(r.y) : "l"(v)); return r;
}
// monotone float -> uint (order-preserving)
__device__ __forceinline__ unsigned ford(float v) {
    unsigned u = __float_as_uint(v);
    return (u & 0x80000000u) ? ~u : (u | 0x80000000u);
}

// -------- scratch (no allocations allowed) --------
__device__ float  g_feat[BATCH * CTOT * 3 * NPT];        // [B][169][3][N]
__device__ int    g_idx[BATCH * NPT * KNN];
__device__ float2 g_y  [BATCH * NPT * MAXCOUT * 3];      // [pt][o][f] {yf,yd}
__device__ float2 g_cmb[BATCH * NPT * MAXCOUT * 3];      // [pt][o][f] {pc-yf, dc-yd}

// ================= knn (fused xx) + REDUX top-k =================
// key_j = 2*dot(xi,xj) - xx_j  (row-constant xx_i dropped; ranking unchanged)
template <int D>
__global__ void knn_kernel(const float* __restrict__ cur, int Ctot, int coff)
{
    const int TI = 8;
    __shared__ u64   sxp[D][4];        // query features packed in row-pairs
    __shared__ float sdist[TI][NPT];

    int b  = blockIdx.x / (NPT / TI);
    int i0 = (blockIdx.x % (NPT / TI)) * TI;
    int tid = threadIdx.x;
    const float* base = cur + (size_t)(b * Ctot + coff) * 3 * NPT;

    for (int f = tid; f < D; f += 256) {
        float q0 = base[f * NPT + i0 + 0], q1 = base[f * NPT + i0 + 1];
        float q2 = base[f * NPT + i0 + 2], q3 = base[f * NPT + i0 + 3];
        float q4 = base[f * NPT + i0 + 4], q5 = base[f * NPT + i0 + 5];
        float q6 = base[f * NPT + i0 + 6], q7 = base[f * NPT + i0 + 7];
        sxp[f][0] = pk2(q0, q1); sxp[f][1] = pk2(q2, q3);
        sxp[f][2] = pk2(q4, q5); sxp[f][3] = pk2(q6, q7);
    }
    __syncthreads();

    // ---- distance phase: thread handles 4 contiguous j (one LDG.128 per f) ----
    {
        int j0 = tid * 4;
        u64 acc[4][4];                 // [rowpair][j]
        float xx[4] = {0.f, 0.f, 0.f, 0.f};
        #pragma unroll
        for (int rp = 0; rp < 4; rp++)
            #pragma unroll
            for (int jj = 0; jj < 4; jj++) acc[rp][jj] = 0ull;

        #pragma unroll 4
        for (int f = 0; f < D; f++) {
            float4 xv = *(const float4*)(base + f * NPT + j0);
            u64 xp[4] = { pk2(xv.x, xv.x), pk2(xv.y, xv.y),
                          pk2(xv.z, xv.z), pk2(xv.w, xv.w) };
            u64 q0 = sxp[f][0], q1 = sxp[f][1], q2 = sxp[f][2], q3 = sxp[f][3];
            #pragma unroll
            for (int jj = 0; jj < 4; jj++) {
                fma2(acc[0][jj], q0, xp[jj]);
                fma2(acc[1][jj], q1, xp[jj]);
                fma2(acc[2][jj], q2, xp[jj]);
                fma2(acc[3][jj], q3, xp[jj]);
            }
            xx[0] = fmaf(xv.x, xv.x, xx[0]);
            xx[1] = fmaf(xv.y, xv.y, xx[1]);
            xx[2] = fmaf(xv.z, xv.z, xx[2]);
            xx[3] = fmaf(xv.w, xv.w, xx[3]);
        }
        #pragma unroll
        for (int rp = 0; rp < 4; rp++)
            #pragma unroll
            for (int jj = 0; jj < 4; jj++) {
                float2 v = up2(acc[rp][jj]);
                sdist[2 * rp]     [j0 + jj] = 2.f * v.x - xx[jj];
                sdist[2 * rp + 1] [j0 + jj] = 2.f * v.y - xx[jj];
            }
    }
    __syncthreads();

    // ---- top-k: warp w handles row w; HW REDUX argmax, lazy lane rescan ----
    int w = tid >> 5, lane = tid & 31;
    float* row = sdist[w];
    int ob = (b * NPT + i0 + w) * KNN;

    float lb = -FLT_MAX; int lbi = 0x7fffffff;
    #pragma unroll 4
    for (int t = 0; t < 32; t++) {
        float v = row[lane + 32 * t];
        if (v > lb) { lb = v; lbi = lane + 32 * t; }
    }
    for (int it = 0; it < KNN; it++) {
        unsigned key = ford(lb);
        unsigned mx  = __reduce_max_sync(0xffffffffu, key);
        int cand = (key == mx) ? lbi : 0x7fffffff;
        int wbi  = __reduce_min_sync(0xffffffffu, cand);   // smallest idx on ties
        if (lane == 0) g_idx[ob + it] = wbi;
        if (lbi == wbi) {                                  // this lane owned winner
            row[wbi] = -FLT_MAX;
            lb = -FLT_MAX; lbi = 0x7fffffff;
            #pragma unroll 4
            for (int t = 0; t < 32; t++) {
                float v = row[lane + 32 * t];
                if (v > lb) { lb = v; lbi = lane + 32 * t; }
            }
        }
    }
}

// ================= per-point linear maps =================
template <int CIN, int COUT>
__global__ void ymap_kernel(const float* __restrict__ cur, int Ctot, int coff,
                            const float* __restrict__ Wf, const float* __restrict__ Wd)
{
    const int IN2 = 2 * CIN;
    extern __shared__ float sm[];
    float4* sW = (float4*)sm;                 // [CIN][COUT] {wfL,wdL,wfR,wdR}
    float*  sx = sm + 4 * CIN * COUT;         // [3*CIN][32]

    int tid = threadIdx.x;
    int nn = tid & 31, og = tid >> 5;
    int pt0 = blockIdx.x * 32;
    int b = pt0 >> 10, n0 = pt0 & (NPT - 1);
    const float* base = cur + (size_t)(b * Ctot + coff) * 3 * NPT;

    for (int t = tid; t < CIN * COUT; t += blockDim.x) {
        int c = t / COUT, o = t - c * COUT;
        sW[t] = make_float4(Wf[o * IN2 + c], Wd[o * IN2 + c],
                            Wf[o * IN2 + CIN + c], Wd[o * IN2 + CIN + c]);
    }
    for (int t = tid; t < 3 * CIN * 32; t += blockDim.x) {
        int row = t >> 5, col = t & 31;
        sx[t] = base[row * NPT + n0 + col];
    }
    __syncthreads();

    int pt = pt0 + nn;
    for (int o = og; o < COUT; o += 8) {
        u64 accL0 = 0ull, accL1 = 0ull, accL2 = 0ull;
        u64 accR0 = 0ull, accR1 = 0ull, accR2 = 0ull;
        for (int c = 0; c < CIN; c++) {
            float4 w = sW[c * COUT + o];
            u64 wl = pk2(w.x, w.y);
            u64 wr = pk2(w.z, w.w);
            float x0 = sx[(c * 3 + 0) * 32 + nn];
            float x1 = sx[(c * 3 + 1) * 32 + nn];
            float x2 = sx[(c * 3 + 2) * 32 + nn];
            u64 p0 = pk2(x0, x0), p1 = pk2(x1, x1), p2 = pk2(x2, x2);
            fma2(accL0, wl, p0); fma2(accR0, wr, p0);
            fma2(accL1, wl, p1); fma2(accR1, wr, p1);
            fma2(accL2, wl, p2); fma2(accR2, wr, p2);
        }
        float2* yo = g_y   + ((size_t)pt * COUT + o) * 3;
        float2* co = g_cmb + ((size_t)pt * COUT + o) * 3;
        float2 l0 = up2(accL0), l1 = up2(accL1), l2 = up2(accL2);
        float2 r0 = up2(accR0), r1 = up2(accR1), r2 = up2(accR2);
        yo[0] = l0; yo[1] = l1; yo[2] = l2;
        co[0] = make_float2(r0.x - l0.x, r0.y - l0.y);
        co[1] = make_float2(r1.x - l1.x, r1.y - l1.y);
        co[2] = make_float2(r2.x - l2.x, r2.y - l2.y);
    }
}

// ================= gather + leaky combine + mean over k =================
template <int COUT, int P, int TPB>
__global__ void pair_kernel(int ooff)
{
    __shared__ int sidx[P][KNN];
    int tid = threadIdx.x;
    int pt0 = blockIdx.x * P;

    for (int t = tid; t < P * KNN; t += TPB) {
        int p = t / KNN;
        if (pt0 + p < TOTPT) sidx[p][t - p * KNN] = g_idx[(pt0 + p) * KNN + (t - p * KNN)];
    }
    __syncthreads();

    int ln = tid / COUT, o = tid - ln * COUT;
    int pt = pt0 + ln;
    if (ln >= P || pt >= TOTPT) return;
    int b = pt >> 10, n = pt & (NPT - 1);

    const float2* cmb = g_cmb + ((size_t)pt * COUT + o) * 3;
    float2 c0 = cmb[0], c1 = cmb[1], c2 = cmb[2];

    float a0 = 0.f, a1 = 0.f, a2 = 0.f;
    #pragma unroll 5
    for (int j = 0; j < KNN; j++) {
        int nj = sidx[ln][j];
        const float2* y = g_y + (((size_t)(b << 10) + nj) * COUT + o) * 3;
        float2 y0 = y[0], y1 = y[1], y2 = y[2];
        float P0 = y0.x + c0.x, D0 = y0.y + c0.y;
        float P1 = y1.x + c1.x, D1 = y1.y + c1.y;
        float P2 = y2.x + c2.x, D2 = y2.y + c2.y;
        float dot = P0 * D0 + P1 * D1 + P2 * D2;
        float dsq = D0 * D0 + D1 * D1 + D2 * D2;
        float s = dot / (dsq + EPSV);
        float s0, s1, s2;
        if (dot >= 0.f) { s0 = P0; s1 = P1; s2 = P2; }
        else { s0 = P0 - s * D0; s1 = P1 - s * D1; s2 = P2 - s * D2; }
        a0 += 0.2f * P0 + 0.8f * s0;
        a1 += 0.2f * P1 + 0.8f * s1;
        a2 += 0.2f * P2 + 0.8f * s2;
    }
    const float invK = 1.f / KNN;
    float* fo = g_feat + (((size_t)b * CTOT + ooff + o) * 3) * NPT + n;
    fo[0 * NPT] = a0 * invK;
    fo[1 * NPT] = a1 * invK;
    fo[2 * NPT] = a2 * invK;
}

// ========== final VN layer + mean over N (n-pair f32x2 packed) ==========
__global__ void final_kernel(const float* __restrict__ Wf, const float* __restrict__ Wd,
                             float* __restrict__ out)
{
    const int OT = 11;               // 341 = 31 * 11
    const int CI = CTOT;
    __shared__ u64   sWfp[OT * CI];  // {w,w}
    __shared__ u64   sWdp[CI];
    __shared__ float sacc[OT * 3];
    int b  = blockIdx.x / 31;
    int o0 = (blockIdx.x % 31) * OT;
    int tid = threadIdx.x;

    for (int t = tid; t < OT * CI; t += 256) {
        int o = t / CI, c = t - o * CI;
        float w = Wf[(o0 + o) * CI + c];
        sWfp[t] = pk2(w, w);
    }
    for (int t = tid; t < CI; t += 256) { float w = Wd[t]; sWdp[t] = pk2(w, w); }
    if (tid < OT * 3) sacc[tid] = 0.f;
    __syncthreads();

    float sum[OT][3];
    #pragma unroll
    for (int o = 0; o < OT; o++) { sum[o][0] = sum[o][1] = sum[o][2] = 0.f; }

    const float* fb = g_feat + (size_t)b * CTOT * 3 * NPT;
    for (int it = 0; it < 2; it++) {
        int n = 2 * (tid + it * 256);          // even, n and n+1 packed
        u64 p0[OT], p1[OT], p2[OT];
        u64 d0 = 0ull, d1 = 0ull, d2 = 0ull;
        #pragma unroll
        for (int o = 0; o < OT; o++) { p0[o] = p1[o] = p2[o] = 0ull; }

        for (int c = 0; c < CI; c++) {
            u64 x0 = *(const u64*)(fb + (c * 3 + 0) * NPT + n);
            u64 x1 = *(const u64*)(fb + (c * 3 + 1) * NPT + n);
            u64 x2 = *(const u64*)(fb + (c * 3 + 2) * NPT + n);
            u64 wd = sWdp[c];
            fma2(d0, wd, x0); fma2(d1, wd, x1); fma2(d2, wd, x2);
            #pragma unroll
            for (int o = 0; o < OT; o++) {
                u64 wf = sWfp[o * CI + c];
                fma2(p0[o], wf, x0); fma2(p1[o], wf, x1); fma2(p2[o], wf, x2);
            }
        }
        float2 D0 = up2(d0), D1 = up2(d1), D2 = up2(d2);
        float invA = 1.f / (D0.x * D0.x + D1.x * D1.x + D2.x * D2.x + EPSV);
        float invB = 1.f / (D0.y * D0.y + D1.y * D1.y + D2.y * D2.y + EPSV);
        #pragma unroll
        for (int o = 0; o < OT; o++) {
            float2 P0 = up2(p0[o]), P1 = up2(p1[o]), P2 = up2(p2[o]);
            {   // lane n
                float dot = P0.x * D0.x + P1.x * D1.x + P2.x * D2.x;
                float s0, s1, s2;
                if (dot >= 0.f) { s0 = P0.x; s1 = P1.x; s2 = P2.x; }
                else {
                    float sc = dot * invA;
                    s0 = P0.x - sc * D0.x; s1 = P1.x - sc * D1.x; s2 = P2.x - sc * D2.x;
                }
                sum[o][0] += 0.2f * P0.x + 0.8f * s0;
                sum[o][1] += 0.2f * P1.x + 0.8f * s1;
                sum[o][2] += 0.2f * P2.x + 0.8f * s2;
            }
            {   // lane n+1
                float dot = P0.y * D0.y + P1.y * D1.y + P2.y * D2.y;
                float s0, s1, s2;
                if (dot >= 0.f) { s0 = P0.y; s1 = P1.y; s2 = P2.y; }
                else {
                    float sc = dot * invB;
                    s0 = P0.y - sc * D0.y; s1 = P1.y - sc * D1.y; s2 = P2.y - sc * D2.y;
                }
                sum[o][0] += 0.2f * P0.y + 0.8f * s0;
                sum[o][1] += 0.2f * P1.y + 0.8f * s1;
                sum[o][2] += 0.2f * P2.y + 0.8f * s2;
            }
        }
    }
    #pragma unroll
    for (int o = 0; o < OT; o++)
        #pragma unroll
        for (int dd = 0; dd < 3; dd++) {
            float v = sum[o][dd];
            #pragma unroll
            for (int s = 16; s; s >>= 1) v += __shfl_down_sync(0xffffffffu, v, s);
            if ((tid & 31) == 0) atomicAdd(&sacc[o * 3 + dd], v);
        }
    __syncthreads();
    if (tid < OT * 3) out[b * 1023 + o0 * 3 + tid] = sacc[tid] * (1.f / NPT);
}

// ================= launch =================
static constexpr size_t ymap_smem(int CIN, int COUT)
{
    return (size_t)(4 * CIN * COUT + 3 * CIN * 32) * 4;
}

extern "C" void kernel_launch(void* const* d_in, const int* in_sizes, int n_in,
                              void* d_out, int out_size)
{
    const float* x   = (const float*)d_in[0];
    const float* Wf0 = (const float*)d_in[1];
    const float* Wd0 = (const float*)d_in[2];
    const float* Wf1 = (const float*)d_in[3];
    const float* Wd1 = (const float*)d_in[4];
    const float* Wf2 = (const float*)d_in[5];
    const float* Wd2 = (const float*)d_in[6];
    const float* Wf3 = (const float*)d_in[7];
    const float* Wd3 = (const float*)d_in[8];
    const float* Wf4 = (const float*)d_in[9];
    const float* Wd4 = (const float*)d_in[10];
    float* out = (float*)d_out;

    float* feat = nullptr;
    cudaGetSymbolAddress((void**)&feat, g_feat);

    static bool attr_done = false;
    if (!attr_done) {
        cudaFuncSetAttribute(ymap_kernel<42, 85>,
                             cudaFuncAttributeMaxDynamicSharedMemorySize,
                             (int)ymap_smem(42, 85));
        attr_done = true;
    }

    const int KNNG = BATCH * (NPT / 8);      // 1024
    const int YG   = TOTPT / 32;             // 256

    // layer 0 : CIN=1, D=3, out=21 -> feat[0:21)
    knn_kernel<3><<<KNNG, 256>>>(x, 1, 0);
    ymap_kernel<1, 21><<<YG, 256, ymap_smem(1, 21)>>>(x, 1, 0, Wf0, Wd0);
    pair_kernel<21, 12, 256><<<(TOTPT + 11) / 12, 256>>>(0);

    // layer 1 : CIN=21, D=63, out=21 -> feat[21:42)
    knn_kernel<63><<<KNNG, 256>>>(feat, CTOT, 0);
    ymap_kernel<21, 21><<<YG, 256, ymap_smem(21, 21)>>>(feat, CTOT, 0, Wf1, Wd1);
    pair_kernel<21, 12, 256><<<(TOTPT + 11) / 12, 256>>>(21);

    // layer 2 : CIN=21, D=63, out=42 -> feat[42:84)
    knn_kernel<63><<<KNNG, 256>>>(feat, CTOT, 21);
    ymap_kernel<21, 42><<<YG, 256, ymap_smem(21, 42)>>>(feat, CTOT, 21, Wf2, Wd2);
    pair_kernel<42, 6, 256><<<(TOTPT + 5) / 6, 256>>>(42);

    // layer 3 : CIN=42, D=126, out=85 -> feat[84:169)
    knn_kernel<126><<<KNNG, 256>>>(feat, CTOT, 42);
    ymap_kernel<42, 85><<<YG, 256, ymap_smem(42, 85)>>>(feat, CTOT, 42, Wf3, Wd3);
    pair_kernel<85, 3, 256><<<(TOTPT + 2) / 3, 256>>>(84);

    // final VN layer on concat [0:169) + mean over N
    final_kernel<<<BATCH * 31, 256>>>(Wf4, Wd4, out);
}

// round 5
// speedup vs baseline: 3.7882x; 1.1197x over previous
#include <cuda_runtime.h>
#include <cfloat>

#define BATCH 8
#define NPT   1024
#define KNN   20
#define EPSV  1e-6f
#define CTOT  169   // 21+21+42+85 concat channels
#define MAXCOUT 85
#define TOTPT (BATCH * NPT)

typedef unsigned long long u64;

// ---- packed f32x2 helpers (sm_10x FFMA2) ----
__device__ __forceinline__ u64 pk2(float lo, float hi) {
    u64 r; asm("mov.b64 %0,{%1,%2};" : "=l"(r) : "f"(lo), "f"(hi)); return r;
}
__device__ __forceinline__ void fma2(u64& d, u64 a, u64 b) {
    asm("fma.rn.f32x2 %0,%1,%2,%0;" : "+l"(d) : "l"(a), "l"(b));
}
__device__ __forceinline__ float2 up2(u64 v) {
    float2 r; asm("mov.b64 {%0,%1},%2;" : "=f"(r.x), "=f"(r.y) : "l"(v)); return r;
}
// monotone float -> uint (order-preserving)
__device__ __forceinline__ unsigned ford(float v) {
    unsigned u = __float_as_uint(v);
    return (u & 0x80000000u) ? ~u : (u | 0x80000000u);
}

// -------- scratch (no allocations allowed) --------
__device__ float  g_feat[BATCH * CTOT * 3 * NPT];        // [B][169][3][N]
__device__ int    g_idx[BATCH * NPT * KNN];
__device__ float2 g_y  [BATCH * NPT * MAXCOUT * 3];      // [pt][o][f] {yf,yd}
__device__ float2 g_cmb[BATCH * NPT * MAXCOUT * 3];      // [pt][o][f] {pc-yf, dc-yd}

// ================= knn (fused xx) + warp-parallel top-k =================
// key_j = 2*dot(xi,xj) - xx_j  (row-constant xx_i dropped; ranking unchanged)
template <int D>
__global__ void knn_kernel(const float* __restrict__ cur, int Ctot, int coff)
{
    const int TI = 8;
    __shared__ u64   sxp[D][4];        // query features packed in row-pairs
    __shared__ float sdist[TI][NPT];

    int b  = blockIdx.x / (NPT / TI);
    int i0 = (blockIdx.x % (NPT / TI)) * TI;
    int tid = threadIdx.x;
    const float* base = cur + (size_t)(b * Ctot + coff) * 3 * NPT;

    for (int f = tid; f < D; f += 256) {
        float q0 = base[f * NPT + i0 + 0], q1 = base[f * NPT + i0 + 1];
        float q2 = base[f * NPT + i0 + 2], q3 = base[f * NPT + i0 + 3];
        float q4 = base[f * NPT + i0 + 4], q5 = base[f * NPT + i0 + 5];
        float q6 = base[f * NPT + i0 + 6], q7 = base[f * NPT + i0 + 7];
        sxp[f][0] = pk2(q0, q1); sxp[f][1] = pk2(q2, q3);
        sxp[f][2] = pk2(q4, q5); sxp[f][3] = pk2(q6, q7);
    }
    __syncthreads();

    // ---- distance phase: thread handles 4 contiguous j (one LDG.128 per f) ----
    {
        int j0 = tid * 4;
        u64 acc[4][4];                 // [rowpair][j]
        float xx[4] = {0.f, 0.f, 0.f, 0.f};
        #pragma unroll
        for (int rp = 0; rp < 4; rp++)
            #pragma unroll
            for (int jj = 0; jj < 4; jj++) acc[rp][jj] = 0ull;

        #pragma unroll 4
        for (int f = 0; f < D; f++) {
            float4 xv = *(const float4*)(base + f * NPT + j0);
            u64 xp[4] = { pk2(xv.x, xv.x), pk2(xv.y, xv.y),
                          pk2(xv.z, xv.z), pk2(xv.w, xv.w) };
            u64 q0 = sxp[f][0], q1 = sxp[f][1], q2 = sxp[f][2], q3 = sxp[f][3];
            #pragma unroll
            for (int jj = 0; jj < 4; jj++) {
                fma2(acc[0][jj], q0, xp[jj]);
                fma2(acc[1][jj], q1, xp[jj]);
                fma2(acc[2][jj], q2, xp[jj]);
                fma2(acc[3][jj], q3, xp[jj]);
            }
            xx[0] = fmaf(xv.x, xv.x, xx[0]);
            xx[1] = fmaf(xv.y, xv.y, xx[1]);
            xx[2] = fmaf(xv.z, xv.z, xx[2]);
            xx[3] = fmaf(xv.w, xv.w, xx[3]);
        }
        #pragma unroll
        for (int rp = 0; rp < 4; rp++)
            #pragma unroll
            for (int jj = 0; jj < 4; jj++) {
                float2 v = up2(acc[rp][jj]);
                sdist[2 * rp]     [j0 + jj] = 2.f * v.x - xx[jj];
                sdist[2 * rp + 1] [j0 + jj] = 2.f * v.y - xx[jj];
            }
    }
    __syncthreads();

    // ---- top-k: warp w handles row w. Each lane caches argmax of its strip
    //      {lane + 32t}; extraction + owner-strip rescan are warp-parallel. ----
    int w = tid >> 5, lane = tid & 31;
    float* row = sdist[w];
    int ob = (b * NPT + i0 + w) * KNN;

    unsigned ckey; int cidx;
    {
        float lb = -FLT_MAX; int lbi = 0x7fffffff;
        #pragma unroll 8
        for (int t = 0; t < 32; t++) {
            float v = row[lane + 32 * t];
            if (v > lb) { lb = v; lbi = lane + 32 * t; }   // ascending t => min idx on ties
        }
        ckey = ford(lb); cidx = lbi;
    }
    for (int it = 0; it < KNN; it++) {
        unsigned mx = __reduce_max_sync(0xffffffffu, ckey);
        int cand = (ckey == mx) ? cidx : 0x7fffffff;
        int wbi  = __reduce_min_sync(0xffffffffu, cand);   // smallest idx on ties
        if (lane == 0) {
            g_idx[ob + it] = wbi;
            row[wbi] = -FLT_MAX;
        }
        __syncwarp();
        int owner = wbi & 31;
        // warp-parallel rescan of owner's strip
        float v = row[owner + 32 * lane];
        unsigned k2 = ford(v);
        unsigned m2 = __reduce_max_sync(0xffffffffu, k2);
        int c2 = (k2 == m2) ? (owner + 32 * lane) : 0x7fffffff;
        int i2 = __reduce_min_sync(0xffffffffu, c2);
        if (lane == owner) { ckey = m2; cidx = i2; }
    }
}

// ================= per-point linear maps =================
template <int CIN, int COUT>
__global__ void ymap_kernel(const float* __restrict__ cur, int Ctot, int coff,
                            const float* __restrict__ Wf, const float* __restrict__ Wd)
{
    const int IN2 = 2 * CIN;
    extern __shared__ float sm[];
    float4* sW = (float4*)sm;                 // [CIN][COUT] {wfL,wdL,wfR,wdR}
    float*  sx = sm + 4 * CIN * COUT;         // [3*CIN][32]

    int tid = threadIdx.x;
    int nn = tid & 31, og = tid >> 5;
    int pt0 = blockIdx.x * 32;
    int b = pt0 >> 10, n0 = pt0 & (NPT - 1);
    const float* base = cur + (size_t)(b * Ctot + coff) * 3 * NPT;

    for (int t = tid; t < CIN * COUT; t += blockDim.x) {
        int c = t / COUT, o = t - c * COUT;
        sW[t] = make_float4(Wf[o * IN2 + c], Wd[o * IN2 + c],
                            Wf[o * IN2 + CIN + c], Wd[o * IN2 + CIN + c]);
    }
    for (int t = tid; t < 3 * CIN * 32; t += blockDim.x) {
        int row = t >> 5, col = t & 31;
        sx[t] = base[row * NPT + n0 + col];
    }
    __syncthreads();

    int pt = pt0 + nn;
    for (int o = og; o < COUT; o += 8) {
        u64 accL0 = 0ull, accL1 = 0ull, accL2 = 0ull;
        u64 accR0 = 0ull, accR1 = 0ull, accR2 = 0ull;
        for (int c = 0; c < CIN; c++) {
            float4 w = sW[c * COUT + o];
            u64 wl = pk2(w.x, w.y);
            u64 wr = pk2(w.z, w.w);
            float x0 = sx[(c * 3 + 0) * 32 + nn];
            float x1 = sx[(c * 3 + 1) * 32 + nn];
            float x2 = sx[(c * 3 + 2) * 32 + nn];
            u64 p0 = pk2(x0, x0), p1 = pk2(x1, x1), p2 = pk2(x2, x2);
            fma2(accL0, wl, p0); fma2(accR0, wr, p0);
            fma2(accL1, wl, p1); fma2(accR1, wr, p1);
            fma2(accL2, wl, p2); fma2(accR2, wr, p2);
        }
        float2* yo = g_y   + ((size_t)pt * COUT + o) * 3;
        float2* co = g_cmb + ((size_t)pt * COUT + o) * 3;
        float2 l0 = up2(accL0), l1 = up2(accL1), l2 = up2(accL2);
        float2 r0 = up2(accR0), r1 = up2(accR1), r2 = up2(accR2);
        yo[0] = l0; yo[1] = l1; yo[2] = l2;
        co[0] = make_float2(r0.x - l0.x, r0.y - l0.y);
        co[1] = make_float2(r1.x - l1.x, r1.y - l1.y);
        co[2] = make_float2(r2.x - l2.x, r2.y - l2.y);
    }
}

// ================= gather + leaky combine + mean over k =================
template <int COUT, int P, int TPB>
__global__ void pair_kernel(int ooff)
{
    __shared__ int sidx[P][KNN];
    int tid = threadIdx.x;
    int pt0 = blockIdx.x * P;

    for (int t = tid; t < P * KNN; t += TPB) {
        int p = t / KNN;
        if (pt0 + p < TOTPT) sidx[p][t - p * KNN] = g_idx[(pt0 + p) * KNN + (t - p * KNN)];
    }
    __syncthreads();

    int ln = tid / COUT, o = tid - ln * COUT;
    int pt = pt0 + ln;
    if (ln >= P || pt >= TOTPT) return;
    int b = pt >> 10, n = pt & (NPT - 1);

    const float2* cmb = g_cmb + ((size_t)pt * COUT + o) * 3;
    float2 c0 = cmb[0], c1 = cmb[1], c2 = cmb[2];

    float a0 = 0.f, a1 = 0.f, a2 = 0.f;
    #pragma unroll 5
    for (int j = 0; j < KNN; j++) {
        int nj = sidx[ln][j];
        const float2* y = g_y + (((size_t)(b << 10) + nj) * COUT + o) * 3;
        float2 y0 = y[0], y1 = y[1], y2 = y[2];
        float P0 = y0.x + c0.x, D0 = y0.y + c0.y;
        float P1 = y1.x + c1.x, D1 = y1.y + c1.y;
        float P2 = y2.x + c2.x, D2 = y2.y + c2.y;
        float dot = P0 * D0 + P1 * D1 + P2 * D2;
        float dsq = D0 * D0 + D1 * D1 + D2 * D2;
        float s = dot / (dsq + EPSV);
        float s0, s1, s2;
        if (dot >= 0.f) { s0 = P0; s1 = P1; s2 = P2; }
        else { s0 = P0 - s * D0; s1 = P1 - s * D1; s2 = P2 - s * D2; }
        a0 += 0.2f * P0 + 0.8f * s0;
        a1 += 0.2f * P1 + 0.8f * s1;
        a2 += 0.2f * P2 + 0.8f * s2;
    }
    const float invK = 1.f / KNN;
    float* fo = g_feat + (((size_t)b * CTOT + ooff + o) * 3) * NPT + n;
    fo[0 * NPT] = a0 * invK;
    fo[1 * NPT] = a1 * invK;
    fo[2 * NPT] = a2 * invK;
}

// ========== final VN layer + mean over N (n-pair f32x2 packed) ==========
__global__ void final_kernel(const float* __restrict__ Wf, const float* __restrict__ Wd,
                             float* __restrict__ out)
{
    const int OT = 11;               // 341 = 31 * 11
    const int CI = CTOT;
    __shared__ u64   sWfp[OT * CI];  // {w,w}
    __shared__ u64   sWdp[CI];
    __shared__ float sacc[OT * 3];
    int b  = blockIdx.x / 31;
    int o0 = (blockIdx.x % 31) * OT;
    int tid = threadIdx.x;

    for (int t = tid; t < OT * CI; t += 256) {
        int o = t / CI, c = t - o * CI;
        float w = Wf[(o0 + o) * CI + c];
        sWfp[t] = pk2(w, w);
    }
    for (int t = tid; t < CI; t += 256) { float w = Wd[t]; sWdp[t] = pk2(w, w); }
    if (tid < OT * 3) sacc[tid] = 0.f;
    __syncthreads();

    float sum[OT][3];
    #pragma unroll
    for (int o = 0; o < OT; o++) { sum[o][0] = sum[o][1] = sum[o][2] = 0.f; }

    const float* fb = g_feat + (size_t)b * CTOT * 3 * NPT;
    for (int it = 0; it < 2; it++) {
        int n = 2 * (tid + it * 256);          // even, n and n+1 packed
        u64 p0[OT], p1[OT], p2[OT];
        u64 d0 = 0ull, d1 = 0ull, d2 = 0ull;
        #pragma unroll
        for (int o = 0; o < OT; o++) { p0[o] = p1[o] = p2[o] = 0ull; }

        for (int c = 0; c < CI; c++) {
            u64 x0 = *(const u64*)(fb + (c * 3 + 0) * NPT + n);
            u64 x1 = *(const u64*)(fb + (c * 3 + 1) * NPT + n);
            u64 x2 = *(const u64*)(fb + (c * 3 + 2) * NPT + n);
            u64 wd = sWdp[c];
            fma2(d0, wd, x0); fma2(d1, wd, x1); fma2(d2, wd, x2);
            #pragma unroll
            for (int o = 0; o < OT; o++) {
                u64 wf = sWfp[o * CI + c];
                fma2(p0[o], wf, x0); fma2(p1[o], wf, x1); fma2(p2[o], wf, x2);
            }
        }
        float2 D0 = up2(d0), D1 = up2(d1), D2 = up2(d2);
        float invA = 1.f / (D0.x * D0.x + D1.x * D1.x + D2.x * D2.x + EPSV);
        float invB = 1.f / (D0.y * D0.y + D1.y * D1.y + D2.y * D2.y + EPSV);
        #pragma unroll
        for (int o = 0; o < OT; o++) {
            float2 P0 = up2(p0[o]), P1 = up2(p1[o]), P2 = up2(p2[o]);
            {
                float dot = P0.x * D0.x + P1.x * D1.x + P2.x * D2.x;
                float s0, s1, s2;
                if (dot >= 0.f) { s0 = P0.x; s1 = P1.x; s2 = P2.x; }
                else {
                    float sc = dot * invA;
                    s0 = P0.x - sc * D0.x; s1 = P1.x - sc * D1.x; s2 = P2.x - sc * D2.x;
                }
                sum[o][0] += 0.2f * P0.x + 0.8f * s0;
                sum[o][1] += 0.2f * P1.x + 0.8f * s1;
                sum[o][2] += 0.2f * P2.x + 0.8f * s2;
            }
            {
                float dot = P0.y * D0.y + P1.y * D1.y + P2.y * D2.y;
                float s0, s1, s2;
                if (dot >= 0.f) { s0 = P0.y; s1 = P1.y; s2 = P2.y; }
                else {
                    float sc = dot * invB;
                    s0 = P0.y - sc * D0.y; s1 = P1.y - sc * D1.y; s2 = P2.y - sc * D2.y;
                }
                sum[o][0] += 0.2f * P0.y + 0.8f * s0;
                sum[o][1] += 0.2f * P1.y + 0.8f * s1;
                sum[o][2] += 0.2f * P2.y + 0.8f * s2;
            }
        }
    }
    #pragma unroll
    for (int o = 0; o < OT; o++)
        #pragma unroll
        for (int dd = 0; dd < 3; dd++) {
            float v = sum[o][dd];
            #pragma unroll
            for (int s = 16; s; s >>= 1) v += __shfl_down_sync(0xffffffffu, v, s);
            if ((tid & 31) == 0) atomicAdd(&sacc[o * 3 + dd], v);
        }
    __syncthreads();
    if (tid < OT * 3) out[b * 1023 + o0 * 3 + tid] = sacc[tid] * (1.f / NPT);
}

// ================= launch =================
static constexpr size_t ymap_smem(int CIN, int COUT)
{
    return (size_t)(4 * CIN * COUT + 3 * CIN * 32) * 4;
}

extern "C" void kernel_launch(void* const* d_in, const int* in_sizes, int n_in,
                              void* d_out, int out_size)
{
    const float* x   = (const float*)d_in[0];
    const float* Wf0 = (const float*)d_in[1];
    const float* Wd0 = (const float*)d_in[2];
    const float* Wf1 = (const float*)d_in[3];
    const float* Wd1 = (const float*)d_in[4];
    const float* Wf2 = (const float*)d_in[5];
    const float* Wd2 = (const float*)d_in[6];
    const float* Wf3 = (const float*)d_in[7];
    const float* Wd3 = (const float*)d_in[8];
    const float* Wf4 = (const float*)d_in[9];
    const float* Wd4 = (const float*)d_in[10];
    float* out = (float*)d_out;

    float* feat = nullptr;
    cudaGetSymbolAddress((void**)&feat, g_feat);

    static bool attr_done = false;
    if (!attr_done) {
        cudaFuncSetAttribute(ymap_kernel<42, 85>,
                             cudaFuncAttributeMaxDynamicSharedMemorySize,
                             (int)ymap_smem(42, 85));
        attr_done = true;
    }

    const int KNNG = BATCH * (NPT / 8);      // 1024
    const int YG   = TOTPT / 32;             // 256

    // layer 0 : CIN=1, D=3, out=21 -> feat[0:21)
    knn_kernel<3><<<KNNG, 256>>>(x, 1, 0);
    ymap_kernel<1, 21><<<YG, 256, ymap_smem(1, 21)>>>(x, 1, 0, Wf0, Wd0);
    pair_kernel<21, 12, 256><<<(TOTPT + 11) / 12, 256>>>(0);

    // layer 1 : CIN=21, D=63, out=21 -> feat[21:42)
    knn_kernel<63><<<KNNG, 256>>>(feat, CTOT, 0);
    ymap_kernel<21, 21><<<YG, 256, ymap_smem(21, 21)>>>(feat, CTOT, 0, Wf1, Wd1);
    pair_kernel<21, 12, 256><<<(TOTPT + 11) / 12, 256>>>(21);

    // layer 2 : CIN=21, D=63, out=42 -> feat[42:84)
    knn_kernel<63><<<KNNG, 256>>>(feat, CTOT, 21);
    ymap_kernel<21, 42><<<YG, 256, ymap_smem(21, 42)>>>(feat, CTOT, 21, Wf2, Wd2);
    pair_kernel<42, 6, 256><<<(TOTPT + 5) / 6, 256>>>(42);

    // layer 3 : CIN=42, D=126, out=85 -> feat[84:169)
    knn_kernel<126><<<KNNG, 256>>>(feat, CTOT, 42);
    ymap_kernel<42, 85><<<YG, 256, ymap_smem(42, 85)>>>(feat, CTOT, 42, Wf3, Wd3);
    pair_kernel<85, 3, 256><<<(TOTPT + 2) / 3, 256>>>(84);

    // final VN layer on concat [0:169) + mean over N
    final_kernel<<<BATCH * 31, 256>>>(Wf4, Wd4, out);
}